// round 2
// baseline (speedup 1.0000x reference)
#include <cuda_runtime.h>
#include <cuda_bf16.h>
#include <math.h>

// Problem constants (fixed by the dataset)
#define NN      10000        // nodes
#define EE      160000       // edges (before self loops)
#define ETOT    (EE + NN)    // edges incl self loops
#define IND     512
#define HID     128
#define HEADS   8
#define D1      (HEADS*HID)  // 1024
#define EMB     256

// ---------------- scratch (static __device__, no allocation) ----------------
__device__ float g_h1  [NN * D1];     // layer1 features after GEMM1
__device__ float g_acc1[NN * D1];     // layer1 unnormalized aggregation / h1e after ELU
__device__ float g_as1 [NN * HEADS];
__device__ float g_ad1 [NN * HEADS];
__device__ float g_m1  [NN * HEADS];
__device__ float g_den1[NN * HEADS];
__device__ float g_e1  [ETOT * HEADS];
__device__ float g_h2  [NN * EMB];
__device__ float g_as2 [NN];
__device__ float g_ad2 [NN];
__device__ float g_m2  [NN];
__device__ float g_den2[NN];
__device__ float g_e2  [ETOT];

// ---------------- helpers ----------------
__device__ __forceinline__ void atomicMaxF(float* addr, float v) {
    if (v >= 0.f) atomicMax((int*)addr, __float_as_int(v));
    else          atomicMin((unsigned int*)addr, __float_as_uint(v));
}

__device__ __forceinline__ void redAdd4(float* addr, float4 v) {
    asm volatile("red.global.add.v4.f32 [%0], {%1,%2,%3,%4};"
                 :: "l"(addr), "f"(v.x), "f"(v.y), "f"(v.z), "f"(v.w)
                 : "memory");
}

// ---------------- zero kernel ----------------
__global__ void zero_kernel(float4* p, int n4) {
    int i = blockIdx.x * blockDim.x + threadIdx.x;
    if (i < n4) p[i] = make_float4(0.f, 0.f, 0.f, 0.f);
}

// ---------------- tiled fp32 SGEMM: C[M,N] = A[M,K] @ B[K,N] ----------------
// BM=128, BN=128, BK=8, 256 threads, 8x8 per-thread microtile
template<int BM, int BN, int BK, int TM, int TN>
__global__ void sgemm_kernel(const float* __restrict__ A, const float* __restrict__ B,
                             float* __restrict__ C, int M, int N, int K) {
    __shared__ float As[BK][BM];
    __shared__ float Bs[BK][BN];
    const int tid = threadIdx.x;
    const int aRow0 = blockIdx.y * BM;
    const int bCol0 = blockIdx.x * BN;
    const int trow = (tid / (BN / TN)) * TM;   // BN/TN = 16
    const int tcol = (tid % (BN / TN)) * TN;

    float acc[TM][TN];
    #pragma unroll
    for (int i = 0; i < TM; i++)
        #pragma unroll
        for (int j = 0; j < TN; j++) acc[i][j] = 0.f;

    const int aLdRow = tid / (BK / 4);        // 0..127
    const int aLdCol = (tid % (BK / 4)) * 4;  // 0 or 4
    const int bLdRow = tid / (BN / 4);        // 0..7
    const int bLdCol = (tid % (BN / 4)) * 4;  // 0..124

    for (int k0 = 0; k0 < K; k0 += BK) {
        float4 av = make_float4(0.f, 0.f, 0.f, 0.f);
        int ar = aRow0 + aLdRow;
        if (ar < M) av = *(const float4*)&A[(size_t)ar * K + k0 + aLdCol];
        As[aLdCol + 0][aLdRow] = av.x;
        As[aLdCol + 1][aLdRow] = av.y;
        As[aLdCol + 2][aLdRow] = av.z;
        As[aLdCol + 3][aLdRow] = av.w;
        float4 bv = *(const float4*)&B[(size_t)(k0 + bLdRow) * N + bCol0 + bLdCol];
        *(float4*)&Bs[bLdRow][bLdCol] = bv;
        __syncthreads();

        #pragma unroll
        for (int kk = 0; kk < BK; kk++) {
            float4 a0 = *(const float4*)&As[kk][trow];
            float4 a1 = *(const float4*)&As[kk][trow + 4];
            float4 b0 = *(const float4*)&Bs[kk][tcol];
            float4 b1 = *(const float4*)&Bs[kk][tcol + 4];
            float ra[TM] = {a0.x, a0.y, a0.z, a0.w, a1.x, a1.y, a1.z, a1.w};
            float rb[TN] = {b0.x, b0.y, b0.z, b0.w, b1.x, b1.y, b1.z, b1.w};
            #pragma unroll
            for (int i = 0; i < TM; i++)
                #pragma unroll
                for (int j = 0; j < TN; j++)
                    acc[i][j] += ra[i] * rb[j];
        }
        __syncthreads();
    }

    #pragma unroll
    for (int i = 0; i < TM; i++) {
        int r = aRow0 + trow + i;
        if (r >= M) continue;
        #pragma unroll
        for (int j = 0; j < TN; j += 4) {
            float4 v = make_float4(acc[i][j], acc[i][j+1], acc[i][j+2], acc[i][j+3]);
            *(float4*)&C[(size_t)r * N + bCol0 + tcol + j] = v;
        }
    }
}

// ---------------- per-node attention coefficients + init m/den ----------------
// one warp per (node, head); also initializes m=-inf, den=0
template<int H, int C>
__global__ void alphas_kernel(const float* __restrict__ h,
                              const float* __restrict__ a_src, const float* __restrict__ a_dst,
                              float* __restrict__ as_, float* __restrict__ ad_,
                              float* __restrict__ m, float* __restrict__ den, int N) {
    int w = (blockIdx.x * blockDim.x + threadIdx.x) >> 5;
    int lane = threadIdx.x & 31;
    if (w >= N * H) return;
    int n = w / H, hh = w % H;
    const float* hp = h + (size_t)n * H * C + hh * C;
    float s1 = 0.f, s2 = 0.f;
    for (int c = lane; c < C; c += 32) {
        float v = hp[c];
        s1 += v * a_src[hh * C + c];
        s2 += v * a_dst[hh * C + c];
    }
    #pragma unroll
    for (int o = 16; o; o >>= 1) {
        s1 += __shfl_xor_sync(0xFFFFFFFFu, s1, o);
        s2 += __shfl_xor_sync(0xFFFFFFFFu, s2, o);
    }
    if (lane == 0) {
        as_[w] = s1; ad_[w] = s2;
        m[w] = -INFINITY; den[w] = 0.f;
    }
}

// ---------------- edge pass A: leaky-relu + segment max ----------------
template<int H>
__global__ void edge_max_kernel(const int* __restrict__ ei, int E, int N,
                                const float* __restrict__ as_, const float* __restrict__ ad_,
                                float* __restrict__ ebuf, float* __restrict__ m) {
    int idx = blockIdx.x * blockDim.x + threadIdx.x;
    int Etot = E + N;
    if (idx >= Etot * H) return;
    int e = idx / H, h = idx % H;
    int src, dst;
    if (e < E) { src = ei[e]; dst = ei[E + e]; }
    else       { src = dst = e - E; }
    float v = as_[src * H + h] + ad_[dst * H + h];
    v = v > 0.f ? v : 0.2f * v;
    ebuf[idx] = v;
    atomicMaxF(&m[dst * H + h], v);
}

// ---------------- edge pass B (layer 1): exp + denom + weighted scatter ----------------
// one warp per edge; 8 heads x 128 ch = 1024 floats = 8 x float4 per lane
__global__ void edge_aggr1_kernel(const int* __restrict__ ei, int E, int N,
                                  const float* __restrict__ ebuf, const float* __restrict__ m,
                                  float* __restrict__ den,
                                  const float* __restrict__ h1, float* __restrict__ acc) {
    int w = (blockIdx.x * blockDim.x + threadIdx.x) >> 5;
    int lane = threadIdx.x & 31;
    int Etot = E + N;
    if (w >= Etot) return;
    int src, dst;
    if (w < E) { src = ei[w]; dst = ei[E + w]; }
    else       { src = dst = w - E; }
    float ex = 0.f;
    if (lane < HEADS) {
        float e = ebuf[w * HEADS + lane];
        ex = __expf(e - m[dst * HEADS + lane]);
        atomicAdd(&den[dst * HEADS + lane], ex);
    }
    const float4* hs = (const float4*)(h1 + (size_t)src * D1);
    float4* ad = (float4*)(acc + (size_t)dst * D1);
    #pragma unroll
    for (int h = 0; h < HEADS; h++) {
        float exh = __shfl_sync(0xFFFFFFFFu, ex, h);
        float4 v = hs[h * 32 + lane];
        v.x *= exh; v.y *= exh; v.z *= exh; v.w *= exh;
        redAdd4((float*)&ad[h * 32 + lane], v);
    }
}

// ---------------- normalize + bias + ELU (layer 1, in place) ----------------
__global__ void norm_elu_kernel(float* __restrict__ acc, const float* __restrict__ den,
                                const float* __restrict__ b1, int N) {
    int idx = blockIdx.x * blockDim.x + threadIdx.x;  // per float4
    int total = N * D1 / 4;
    if (idx >= total) return;
    int flat = idx * 4;
    float d = den[flat / HID];          // (n*HEADS + h)
    int cb = flat % D1;
    float4 v = ((float4*)acc)[idx];
    float inv = 1.f / d;
    float x0 = v.x * inv + b1[cb + 0];
    float x1 = v.y * inv + b1[cb + 1];
    float x2 = v.z * inv + b1[cb + 2];
    float x3 = v.w * inv + b1[cb + 3];
    v.x = x0 > 0.f ? x0 : expm1f(x0);
    v.y = x1 > 0.f ? x1 : expm1f(x1);
    v.z = x2 > 0.f ? x2 : expm1f(x2);
    v.w = x3 > 0.f ? x3 : expm1f(x3);
    ((float4*)acc)[idx] = v;
}

// ---------------- edge pass B (layer 2): H=1, C=256 ----------------
__global__ void edge_aggr2_kernel(const int* __restrict__ ei, int E, int N,
                                  const float* __restrict__ ebuf, const float* __restrict__ m,
                                  float* __restrict__ den,
                                  const float* __restrict__ h2, float* __restrict__ out) {
    int w = (blockIdx.x * blockDim.x + threadIdx.x) >> 5;
    int lane = threadIdx.x & 31;
    int Etot = E + N;
    if (w >= Etot) return;
    int src, dst;
    if (w < E) { src = ei[w]; dst = ei[E + w]; }
    else       { src = dst = w - E; }
    float e = ebuf[w];
    float ex = __expf(e - m[dst]);
    if (lane == 0) atomicAdd(&den[dst], ex);
    const float4* hs = (const float4*)(h2 + (size_t)src * EMB);
    float4* ad = (float4*)(out + (size_t)dst * EMB);
    #pragma unroll
    for (int i = 0; i < 2; i++) {
        float4 v = hs[i * 32 + lane];
        v.x *= ex; v.y *= ex; v.z *= ex; v.w *= ex;
        redAdd4((float*)&ad[i * 32 + lane], v);
    }
}

// ---------------- final normalize + bias ----------------
__global__ void final_kernel(float* __restrict__ out, const float* __restrict__ den,
                             const float* __restrict__ b2, int N) {
    int idx = blockIdx.x * blockDim.x + threadIdx.x;   // per float4
    int total = N * EMB / 4;
    if (idx >= total) return;
    int flat = idx * 4;
    float inv = 1.f / den[flat / EMB];
    int cb = flat % EMB;
    float4 v = ((float4*)out)[idx];
    v.x = v.x * inv + b2[cb + 0];
    v.y = v.y * inv + b2[cb + 1];
    v.z = v.z * inv + b2[cb + 2];
    v.w = v.w * inv + b2[cb + 3];
    ((float4*)out)[idx] = v;
}

// ---------------- launch ----------------
extern "C" void kernel_launch(void* const* d_in, const int* in_sizes, int n_in,
                              void* d_out, int out_size) {
    const float* x      = (const float*)d_in[0];
    const int*   ei     = (const int*)d_in[1];     // int32! (JAX x64 disabled)
    const float* W1     = (const float*)d_in[2];
    const float* a_src1 = (const float*)d_in[3];
    const float* a_dst1 = (const float*)d_in[4];
    const float* b1     = (const float*)d_in[5];
    const float* W2     = (const float*)d_in[6];
    const float* a_src2 = (const float*)d_in[7];
    const float* a_dst2 = (const float*)d_in[8];
    const float* b2     = (const float*)d_in[9];
    float* out = (float*)d_out;

    const int N = in_sizes[0] / IND;      // 10000
    const int E = in_sizes[1] / 2;        // 160000
    const int Etot = E + N;

    float *p_h1, *p_acc1, *p_as1, *p_ad1, *p_m1, *p_den1, *p_e1;
    float *p_h2, *p_as2, *p_ad2, *p_m2, *p_den2, *p_e2;
    cudaGetSymbolAddress((void**)&p_h1,   g_h1);
    cudaGetSymbolAddress((void**)&p_acc1, g_acc1);
    cudaGetSymbolAddress((void**)&p_as1,  g_as1);
    cudaGetSymbolAddress((void**)&p_ad1,  g_ad1);
    cudaGetSymbolAddress((void**)&p_m1,   g_m1);
    cudaGetSymbolAddress((void**)&p_den1, g_den1);
    cudaGetSymbolAddress((void**)&p_e1,   g_e1);
    cudaGetSymbolAddress((void**)&p_h2,   g_h2);
    cudaGetSymbolAddress((void**)&p_as2,  g_as2);
    cudaGetSymbolAddress((void**)&p_ad2,  g_ad2);
    cudaGetSymbolAddress((void**)&p_m2,   g_m2);
    cudaGetSymbolAddress((void**)&p_den2, g_den2);
    cudaGetSymbolAddress((void**)&p_e2,   g_e2);

    const int T = 256;

    // zero accumulators
    {
        int n4 = N * D1 / 4;
        zero_kernel<<<(n4 + T - 1) / T, T>>>((float4*)p_acc1, n4);
        int m4 = N * EMB / 4;
        zero_kernel<<<(m4 + T - 1) / T, T>>>((float4*)out, m4);
    }

    // GEMM1: h1 = x @ W1   [N,512]x[512,1024]
    {
        dim3 grid(D1 / 128, (N + 127) / 128);
        sgemm_kernel<128,128,8,8,8><<<grid, 256>>>(x, W1, p_h1, N, D1, IND);
    }

    // attention coefficients layer 1 (+ init m1/den1)
    {
        int warps = N * HEADS;
        alphas_kernel<HEADS, HID><<<(warps * 32 + T - 1) / T, T>>>(
            p_h1, a_src1, a_dst1, p_as1, p_ad1, p_m1, p_den1, N);
    }

    // edge max layer 1
    edge_max_kernel<HEADS><<<(Etot * HEADS + T - 1) / T, T>>>(ei, E, N, p_as1, p_ad1, p_e1, p_m1);

    // edge aggregation layer 1
    edge_aggr1_kernel<<<(Etot * 32 + T - 1) / T, T>>>(ei, E, N, p_e1, p_m1, p_den1, p_h1, p_acc1);

    // normalize + bias + ELU (in place -> h1e in p_acc1)
    {
        int n4 = N * D1 / 4;
        norm_elu_kernel<<<(n4 + T - 1) / T, T>>>(p_acc1, p_den1, b1, N);
    }

    // GEMM2: h2 = h1e @ W2   [N,1024]x[1024,256]
    {
        dim3 grid(EMB / 128, (N + 127) / 128);
        sgemm_kernel<128,128,8,8,8><<<grid, 256>>>(p_acc1, W2, p_h2, N, EMB, D1);
    }

    // attention coefficients layer 2 (+ init m2/den2)
    {
        int warps = N;
        alphas_kernel<1, EMB><<<(warps * 32 + T - 1) / T, T>>>(
            p_h2, a_src2, a_dst2, p_as2, p_ad2, p_m2, p_den2, N);
    }

    // edge max layer 2
    edge_max_kernel<1><<<(Etot + T - 1) / T, T>>>(ei, E, N, p_as2, p_ad2, p_e2, p_m2);

    // edge aggregation layer 2 (into d_out)
    edge_aggr2_kernel<<<(Etot * 32 + T - 1) / T, T>>>(ei, E, N, p_e2, p_m2, p_den2, p_h2, out);

    // final normalize + bias
    {
        int n4 = N * EMB / 4;
        final_kernel<<<(n4 + T - 1) / T, T>>>(out, p_den2, b2, N);
    }
}